// round 4
// baseline (speedup 1.0000x reference)
#include <cuda_runtime.h>
#include <cuda_bf16.h>
#include <cstdint>

#define B_    64
#define S_    512
#define H_    1024
#define HID_  512
#define K3_   3072   // 3*H
#define EPS_  1e-5f
#define NCHUNK 8     // row chunks per span (512/64)
#define CHROWS 64    // rows per chunk
#define KC_   48     // k-chunk per gemm block
#define KT_   64     // number of k-chunks (KC_*KT_ = 3072)

// Scratch (device globals: allocation-free)
__device__ int   g_off[B_ * 5];                // normalized int32 offsets
__device__ float g_sp[B_ * 2 * NCHUNK * H_];   // span partial sums      (4 MB)
__device__ float g_x [B_ * K3_];               // concat embeddings      (768 KB)
__device__ float g_hp[KT_ * B_ * HID_];        // GEMM partial slabs     (8 MB)

// ---------------------------------------------------------------------------
// Kernel 0: normalize offsets (auto-detect int64 vs int32 source).
// ---------------------------------------------------------------------------
__global__ void decode_off(const unsigned int* __restrict__ raw) {
    __shared__ int not64;
    int t = threadIdx.x;                      // 0..319
    if (t == 0) not64 = 0;
    __syncthreads();
    if ((t & 1) && raw[t] != 0u) atomicExch(&not64, 1);
    __syncthreads();
    g_off[t] = not64 ? (int)raw[t] : (int)raw[2 * t];
}

// ---------------------------------------------------------------------------
// Kernel 1: partial span sums. grid (B, 2, NCHUNK), 256 thr, float4/thread.
// ---------------------------------------------------------------------------
__global__ void span_partial(const float* __restrict__ bert) {
    int b  = blockIdx.x;
    int sp = blockIdx.y;
    int z  = blockIdx.z;
    int s0 = g_off[b * 5 + sp * 2];
    int s1 = g_off[b * 5 + sp * 2 + 1];
    int lo = max(s0, z * CHROWS);
    int hi = min(s1, z * CHROWS + CHROWS - 1);

    int t = threadIdx.x;
    float4 acc = make_float4(0.f, 0.f, 0.f, 0.f);
    const float* base = bert + ((size_t)b * S_) * H_ + 4 * t;
    for (int s = lo; s <= hi; ++s) {
        float4 v = *(const float4*)(base + (size_t)s * H_);
        acc.x += v.x; acc.y += v.y; acc.z += v.z; acc.w += v.w;
    }
    float* dst = g_sp + ((size_t)((b * 2 + sp) * NCHUNK + z)) * H_ + 4 * t;
    *(float4*)dst = acc;
}

// ---------------------------------------------------------------------------
// Kernel 2: reduce chunks -> means, gather pronoun row. grid(B), 1024 thr.
// ---------------------------------------------------------------------------
__global__ void finalize_x(const float* __restrict__ bert) {
    int b = blockIdx.x;
    int h = threadIdx.x;
    int a0 = g_off[b * 5 + 0], a1 = g_off[b * 5 + 1];
    int c0 = g_off[b * 5 + 2], c1 = g_off[b * 5 + 3];
    int p  = g_off[b * 5 + 4];
    float inva = 1.0f / (float)(a1 - a0 + 1);
    float invb = 1.0f / (float)(c1 - c0 + 1);

    float sa = 0.f, sb = 0.f;
    #pragma unroll
    for (int z = 0; z < NCHUNK; ++z) {
        sa += g_sp[((size_t)((b * 2 + 0) * NCHUNK + z)) * H_ + h];
        sb += g_sp[((size_t)((b * 2 + 1) * NCHUNK + z)) * H_ + h];
    }
    float* xr = g_x + (size_t)b * K3_;
    xr[h]            = sa * inva;
    xr[H_ + h]       = sb * invb;
    xr[2 * H_ + h]   = bert[((size_t)b * S_ + p) * H_ + h];
}

// ---------------------------------------------------------------------------
// Kernel 3: GEMM x(64x3072) @ W1(3072x512) -> KT_ partial slabs (64x512).
// grid(4 jt x 64 kt), 256 threads. Block tile 64m x 128j x 48k.
// Thread tile 4m x 8j; acc packed f32x2 along j. x pre-duplicated in smem as
// f32x2 pairs so the inner loop is pure LDS.128 + FFMA2 (no packing MOVs),
// all schedulable by ptxas (no volatile).
// ---------------------------------------------------------------------------
__global__ void __launch_bounds__(256) gemm1(const float* __restrict__ W1) {
    __shared__ float  ws[KC_ * 128];            // 24 KB  [k][j]
    __shared__ float2 xs2[KC_ * 64];            // 24 KB  [k][m] duplicated

    int jt  = blockIdx.x;           // 0..3
    int kt  = blockIdx.y;           // 0..63
    int tid = threadIdx.x;
    int jg  = tid & 15;             // 16 j-groups of 8
    int mg  = tid >> 4;             // 16 m-groups of 4
    int k0  = kt * KC_;
    int jb  = jt * 128;

    // load W1 tile [KC_][128] (coalesced float4): 1536 float4 / 256 thr
    for (int i = tid; i < KC_ * 32; i += 256) {
        int r = i >> 5, c = (i & 31) << 2;
        *(float4*)&ws[r * 128 + c] =
            *(const float4*)&W1[(size_t)(k0 + r) * HID_ + jb + c];
    }
    // load x tile transposed + duplicated: g_x[m][k0+k] -> xs2[k][m] = {v,v}
    for (int i = tid; i < 64 * (KC_ / 4); i += 256) {
        int m = i / (KC_ / 4), kq = i % (KC_ / 4);
        float4 v = *(const float4*)&g_x[(size_t)m * K3_ + k0 + kq * 4];
        xs2[(kq * 4 + 0) * 64 + m] = make_float2(v.x, v.x);
        xs2[(kq * 4 + 1) * 64 + m] = make_float2(v.y, v.y);
        xs2[(kq * 4 + 2) * 64 + m] = make_float2(v.z, v.z);
        xs2[(kq * 4 + 3) * 64 + m] = make_float2(v.w, v.w);
    }
    __syncthreads();

    int m0 = mg * 4;
    int j0 = jg * 8;

    unsigned long long acc[4][4];   // [m][j-pair]
    #pragma unroll
    for (int m = 0; m < 4; ++m)
        #pragma unroll
        for (int q = 0; q < 4; ++q) acc[m][q] = 0ull;

    const float*  wbase = ws + j0;
    const float2* xbase = xs2 + m0;

    #pragma unroll 8
    for (int k = 0; k < KC_; ++k) {
        ulonglong2 wa = *(const ulonglong2*)(wbase + k * 128);      // j0..j0+3
        ulonglong2 wb = *(const ulonglong2*)(wbase + k * 128 + 4);  // j0+4..j0+7
        ulonglong2 x01 = *(const ulonglong2*)(xbase + k * 64);      // m0,m0+1
        ulonglong2 x23 = *(const ulonglong2*)(xbase + k * 64 + 2);  // m0+2,m0+3
        unsigned long long w[4] = {wa.x, wa.y, wb.x, wb.y};
        unsigned long long xm[4] = {x01.x, x01.y, x23.x, x23.y};
        #pragma unroll
        for (int m = 0; m < 4; ++m)
            #pragma unroll
            for (int q = 0; q < 4; ++q)
                asm("fma.rn.f32x2 %0, %1, %2, %0;"
                    : "+l"(acc[m][q]) : "l"(w[q]), "l"(xm[m]));
    }

    float* dst = g_hp + (size_t)kt * B_ * HID_;
    #pragma unroll
    for (int m = 0; m < 4; ++m) {
        unsigned long long* row =
            (unsigned long long*)&dst[(size_t)(m0 + m) * HID_ + jb + j0];
        row[0] = acc[m][0];
        row[1] = acc[m][1];
        row[2] = acc[m][2];
        row[3] = acc[m][3];
    }
}

// ---------------------------------------------------------------------------
// Kernel 4: reduce KT_ slabs, BN + leaky, @W2 + b2 -> out[64][3].
// ---------------------------------------------------------------------------
__global__ void head(const float* __restrict__ b1,
                     const float* __restrict__ gamma,
                     const float* __restrict__ beta,
                     const float* __restrict__ rmean,
                     const float* __restrict__ rvar,
                     const float* __restrict__ W2,
                     const float* __restrict__ b2,
                     float* __restrict__ out) {
    int b = blockIdx.x;
    int j = threadIdx.x;               // 0..511

    float s = 0.f;
    #pragma unroll
    for (int p = 0; p < KT_; ++p)
        s += g_hp[(size_t)p * B_ * HID_ + (size_t)b * HID_ + j];

    float sc = gamma[j] * rsqrtf(rvar[j] + EPS_);
    float h  = (s + b1[j] - rmean[j]) * sc + beta[j];
    h = (h >= 0.f) ? h : 0.01f * h;

    float o0 = h * W2[j * 3 + 0];
    float o1 = h * W2[j * 3 + 1];
    float o2 = h * W2[j * 3 + 2];

    #pragma unroll
    for (int d = 16; d > 0; d >>= 1) {
        o0 += __shfl_down_sync(0xFFFFFFFFu, o0, d);
        o1 += __shfl_down_sync(0xFFFFFFFFu, o1, d);
        o2 += __shfl_down_sync(0xFFFFFFFFu, o2, d);
    }

    __shared__ float red[16][3];
    if ((j & 31) == 0) {
        int w = j >> 5;
        red[w][0] = o0; red[w][1] = o1; red[w][2] = o2;
    }
    __syncthreads();
    if (j < 3) {
        float t = 0.f;
        #pragma unroll
        for (int w = 0; w < 16; ++w) t += red[w][j];
        out[b * 3 + j] = t + b2[j];
    }
}

// ---------------------------------------------------------------------------
extern "C" void kernel_launch(void* const* d_in, const int* in_sizes, int n_in,
                              void* d_out, int out_size) {
    const float*        bert  = (const float*)d_in[0];
    const unsigned int* offw  = (const unsigned int*)d_in[1];
    const float*        W1    = (const float*)d_in[2];
    const float*        b1    = (const float*)d_in[3];
    const float*        gamma = (const float*)d_in[4];
    const float*        beta  = (const float*)d_in[5];
    const float*        rmean = (const float*)d_in[6];
    const float*        rvar  = (const float*)d_in[7];
    const float*        W2    = (const float*)d_in[8];
    const float*        b2    = (const float*)d_in[9];
    float* out = (float*)d_out;

    decode_off<<<1, B_ * 5>>>(offw);
    span_partial<<<dim3(B_, 2, NCHUNK), 256>>>(bert);
    finalize_x<<<B_, 1024>>>(bert);
    gemm1<<<dim3(4, KT_), 256>>>(W1);
    head<<<B_, 512>>>(b1, gamma, beta, rmean, rvar, W2, b2, out);
}

// round 5
// speedup vs baseline: 1.1410x; 1.1410x over previous
#include <cuda_runtime.h>
#include <cuda_bf16.h>
#include <cstdint>

#define B_    64
#define S_    512
#define H_    1024
#define HID_  512
#define K3_   3072   // 3*H
#define EPS_  1e-5f
#define NCHUNK 8     // row chunks per span (512/64)
#define CHROWS 64    // rows per chunk
#define KC_   48     // k-chunk per gemm block
#define KT_   64     // number of k-chunks (KC_*KT_ = 3072)

// Scratch (device globals: allocation-free)
__device__ float g_sp[B_ * 2 * NCHUNK * H_];   // span partial sums      (4 MB)
__device__ float g_x [B_ * K3_];               // concat embeddings      (768 KB)
__device__ float g_hp[KT_ * B_ * HID_];        // GEMM partial slabs     (8 MB)

// ---------------------------------------------------------------------------
// Inline offset decode: detect int64 vs int32 source (global scan, L1-hot).
// Must be called by ALL threads of the block (contains __syncthreads).
// ---------------------------------------------------------------------------
__device__ __forceinline__ int off_not64(const unsigned int* __restrict__ raw) {
    __shared__ int flag;
    if (threadIdx.x == 0) flag = 0;
    __syncthreads();
    for (int t = threadIdx.x; t < 160; t += blockDim.x)
        if (raw[2 * t + 1] != 0u) atomicExch(&flag, 1);
    __syncthreads();
    return flag;
}
__device__ __forceinline__ int off_get(const unsigned int* __restrict__ raw,
                                       int not64, int idx) {
    return not64 ? (int)raw[idx] : (int)raw[2 * idx];
}

// ---------------------------------------------------------------------------
// Kernel 1: partial span sums. grid (B, 2, NCHUNK), 256 thr, float4/thread.
// ---------------------------------------------------------------------------
__global__ void span_partial(const float* __restrict__ bert,
                             const unsigned int* __restrict__ raw) {
    int n64 = off_not64(raw);
    int b  = blockIdx.x;
    int sp = blockIdx.y;
    int z  = blockIdx.z;
    int s0 = off_get(raw, n64, b * 5 + sp * 2);
    int s1 = off_get(raw, n64, b * 5 + sp * 2 + 1);
    int lo = max(s0, z * CHROWS);
    int hi = min(s1, z * CHROWS + CHROWS - 1);

    int t = threadIdx.x;
    float4 acc = make_float4(0.f, 0.f, 0.f, 0.f);
    const float* base = bert + ((size_t)b * S_) * H_ + 4 * t;
    #pragma unroll 4
    for (int s = lo; s <= hi; ++s) {
        float4 v = *(const float4*)(base + (size_t)s * H_);
        acc.x += v.x; acc.y += v.y; acc.z += v.z; acc.w += v.w;
    }
    float* dst = g_sp + ((size_t)((b * 2 + sp) * NCHUNK + z)) * H_ + 4 * t;
    *(float4*)dst = acc;
}

// ---------------------------------------------------------------------------
// Kernel 2: reduce chunks -> means, gather pronoun row. grid(B), 1024 thr.
// ---------------------------------------------------------------------------
__global__ void finalize_x(const float* __restrict__ bert,
                           const unsigned int* __restrict__ raw) {
    int n64 = off_not64(raw);
    int b = blockIdx.x;
    int h = threadIdx.x;
    int a0 = off_get(raw, n64, b * 5 + 0), a1 = off_get(raw, n64, b * 5 + 1);
    int c0 = off_get(raw, n64, b * 5 + 2), c1 = off_get(raw, n64, b * 5 + 3);
    int p  = off_get(raw, n64, b * 5 + 4);
    float inva = 1.0f / (float)(a1 - a0 + 1);
    float invb = 1.0f / (float)(c1 - c0 + 1);

    float sa = 0.f, sb = 0.f;
    #pragma unroll
    for (int z = 0; z < NCHUNK; ++z) {
        sa += g_sp[((size_t)((b * 2 + 0) * NCHUNK + z)) * H_ + h];
        sb += g_sp[((size_t)((b * 2 + 1) * NCHUNK + z)) * H_ + h];
    }
    float* xr = g_x + (size_t)b * K3_;
    xr[h]            = sa * inva;
    xr[H_ + h]       = sb * invb;
    xr[2 * H_ + h]   = bert[((size_t)b * S_ + p) * H_ + h];
}

// ---------------------------------------------------------------------------
// Kernel 3: GEMM x(64x3072) @ W1(3072x512) -> KT_ partial slabs (64x512).
// grid(4 jt x 64 kt), 256 threads. Block tile 64m x 128j x 48k.
// Thread tile 4m x 8j; acc packed f32x2. x duplicated in smem ({v,v}),
// conflict-free fills, register double-buffered inner loop.
// ---------------------------------------------------------------------------
#define FMA2(A, W, X) asm("fma.rn.f32x2 %0, %1, %2, %0;" \
                          : "+l"(A) : "l"(W), "l"(X))

__global__ void __launch_bounds__(256) gemm1(const float* __restrict__ W1) {
    __shared__ float  ws[KC_ * 128];            // 24 KB  [k][j]
    __shared__ float2 xs2[KC_ * 64];            // 24 KB  [k][m] duplicated

    int jt  = blockIdx.x;           // 0..3
    int kt  = blockIdx.y;           // 0..63
    int tid = threadIdx.x;
    int jg  = tid & 15;             // 16 j-groups of 8
    int mg  = tid >> 4;             // 16 m-groups of 4
    int k0  = kt * KC_;
    int jb  = jt * 128;

    // W1 tile [KC_][128]: warp reads one full 512B row -> coalesced,
    // smem stores consecutive -> conflict-free.
    #pragma unroll
    for (int it = 0; it < 6; ++it) {
        int i = it * 256 + tid;                 // 0 .. KC_*32-1
        int r = i >> 5, c = (i & 31) << 2;
        *(float4*)&ws[r * 128 + c] =
            *(const float4*)&W1[(size_t)(k0 + r) * HID_ + jb + c];
    }
    // x tile transposed+duplicated: lanes iterate m within fixed kq ->
    // conflict-free STS (consecutive float2 per lane).
    #pragma unroll
    for (int it = 0; it < 3; ++it) {
        int i  = it * 256 + tid;                // 0..767
        int kq = i >> 6;                        // 0..11
        int m  = i & 63;
        float4 v = *(const float4*)&g_x[(size_t)m * K3_ + k0 + kq * 4];
        xs2[(kq * 4 + 0) * 64 + m] = make_float2(v.x, v.x);
        xs2[(kq * 4 + 1) * 64 + m] = make_float2(v.y, v.y);
        xs2[(kq * 4 + 2) * 64 + m] = make_float2(v.z, v.z);
        xs2[(kq * 4 + 3) * 64 + m] = make_float2(v.w, v.w);
    }
    __syncthreads();

    int m0 = mg * 4;
    int j0 = jg * 8;

    unsigned long long acc[4][4];   // [m][j-pair]
    #pragma unroll
    for (int m = 0; m < 4; ++m)
        #pragma unroll
        for (int q = 0; q < 4; ++q) acc[m][q] = 0ull;

    const float*  wp = ws + j0;
    const float2* xp = xs2 + m0;

    // register double-buffer: prefetch k+1 while FMA'ing k
    ulonglong2 cwa = *(const ulonglong2*)(wp);
    ulonglong2 cwb = *(const ulonglong2*)(wp + 4);
    ulonglong2 cxa = *(const ulonglong2*)(xp);
    ulonglong2 cxb = *(const ulonglong2*)(xp + 2);

    #pragma unroll
    for (int k = 0; k < KC_; ++k) {
        ulonglong2 nwa, nwb, nxa, nxb;
        if (k < KC_ - 1) {
            const float*  wn = wp + (k + 1) * 128;
            const float2* xn = xp + (k + 1) * 64;
            nwa = *(const ulonglong2*)(wn);
            nwb = *(const ulonglong2*)(wn + 4);
            nxa = *(const ulonglong2*)(xn);
            nxb = *(const ulonglong2*)(xn + 2);
        }
        unsigned long long w0 = cwa.x, w1 = cwa.y, w2 = cwb.x, w3 = cwb.y;
        unsigned long long x0 = cxa.x, x1 = cxa.y, x2 = cxb.x, x3 = cxb.y;
        FMA2(acc[0][0], w0, x0); FMA2(acc[0][1], w1, x0);
        FMA2(acc[0][2], w2, x0); FMA2(acc[0][3], w3, x0);
        FMA2(acc[1][0], w0, x1); FMA2(acc[1][1], w1, x1);
        FMA2(acc[1][2], w2, x1); FMA2(acc[1][3], w3, x1);
        FMA2(acc[2][0], w0, x2); FMA2(acc[2][1], w1, x2);
        FMA2(acc[2][2], w2, x2); FMA2(acc[2][3], w3, x2);
        FMA2(acc[3][0], w0, x3); FMA2(acc[3][1], w1, x3);
        FMA2(acc[3][2], w2, x3); FMA2(acc[3][3], w3, x3);
        cwa = nwa; cwb = nwb; cxa = nxa; cxb = nxb;
    }

    float* dst = g_hp + (size_t)kt * B_ * HID_;
    #pragma unroll
    for (int m = 0; m < 4; ++m) {
        unsigned long long* row =
            (unsigned long long*)&dst[(size_t)(m0 + m) * HID_ + jb + j0];
        row[0] = acc[m][0];
        row[1] = acc[m][1];
        row[2] = acc[m][2];
        row[3] = acc[m][3];
    }
}

// ---------------------------------------------------------------------------
// Kernel 4: reduce KT_ slabs, BN + leaky, @W2 + b2 -> out[64][3].
// ---------------------------------------------------------------------------
__global__ void head(const float* __restrict__ b1,
                     const float* __restrict__ gamma,
                     const float* __restrict__ beta,
                     const float* __restrict__ rmean,
                     const float* __restrict__ rvar,
                     const float* __restrict__ W2,
                     const float* __restrict__ b2,
                     float* __restrict__ out) {
    int b = blockIdx.x;
    int j = threadIdx.x;               // 0..511

    float s = 0.f;
    #pragma unroll
    for (int p = 0; p < KT_; ++p)
        s += g_hp[(size_t)p * B_ * HID_ + (size_t)b * HID_ + j];

    float sc = gamma[j] * rsqrtf(rvar[j] + EPS_);
    float h  = (s + b1[j] - rmean[j]) * sc + beta[j];
    h = (h >= 0.f) ? h : 0.01f * h;

    float o0 = h * W2[j * 3 + 0];
    float o1 = h * W2[j * 3 + 1];
    float o2 = h * W2[j * 3 + 2];

    #pragma unroll
    for (int d = 16; d > 0; d >>= 1) {
        o0 += __shfl_down_sync(0xFFFFFFFFu, o0, d);
        o1 += __shfl_down_sync(0xFFFFFFFFu, o1, d);
        o2 += __shfl_down_sync(0xFFFFFFFFu, o2, d);
    }

    __shared__ float red[16][3];
    if ((j & 31) == 0) {
        int w = j >> 5;
        red[w][0] = o0; red[w][1] = o1; red[w][2] = o2;
    }
    __syncthreads();
    if (j < 3) {
        float t = 0.f;
        #pragma unroll
        for (int w = 0; w < 16; ++w) t += red[w][j];
        out[b * 3 + j] = t + b2[j];
    }
}

// ---------------------------------------------------------------------------
extern "C" void kernel_launch(void* const* d_in, const int* in_sizes, int n_in,
                              void* d_out, int out_size) {
    const float*        bert  = (const float*)d_in[0];
    const unsigned int* offw  = (const unsigned int*)d_in[1];
    const float*        W1    = (const float*)d_in[2];
    const float*        b1    = (const float*)d_in[3];
    const float*        gamma = (const float*)d_in[4];
    const float*        beta  = (const float*)d_in[5];
    const float*        rmean = (const float*)d_in[6];
    const float*        rvar  = (const float*)d_in[7];
    const float*        W2    = (const float*)d_in[8];
    const float*        b2    = (const float*)d_in[9];
    float* out = (float*)d_out;

    span_partial<<<dim3(B_, 2, NCHUNK), 256>>>(bert, offw);
    finalize_x<<<B_, 1024>>>(bert, offw);
    gemm1<<<dim3(4, KT_), 256>>>(W1);
    head<<<B_, 512>>>(b1, gamma, beta, rmean, rvar, W2, b2, out);
}